// round 3
// baseline (speedup 1.0000x reference)
#include <cuda_runtime.h>
#include <math.h>

#define B_  4
#define S_  2048
#define D_  1024
#define H_  16
#define DH_ 64

// Scratch: q, k in [B,H,S,dh] layout. __device__ globals (no runtime alloc allowed).
__device__ float g_q[B_*H_*S_*DH_];
__device__ float g_k[B_*H_*S_*DH_];

// ---------------------------------------------------------------------------
// Kernel 1: qk = x @ W^T + b  (M=8192, N=2048, K=1024), scatter into g_q/g_k.
// Column j of the 2048-wide output maps to h=j>>7, d=(j&127)>>1, c=j&1 (c=0->q).
// ---------------------------------------------------------------------------
__global__ __launch_bounds__(256)
void gemm_qk_kernel(const float* __restrict__ x, const float* __restrict__ W,
                    const float* __restrict__ bias) {
    __shared__ float As[16][132];
    __shared__ float Bs[16][132];
    const int tid = threadIdx.x;
    const int bn = blockIdx.x;   // 0..15  (N tiles of 128)
    const int bm = blockIdx.y;   // 0..63  (M tiles of 128)
    const int tm = tid >> 4;
    const int tn = tid & 15;

    float acc[8][8];
    #pragma unroll
    for (int i = 0; i < 8; i++)
        #pragma unroll
        for (int j = 0; j < 8; j++) acc[i][j] = 0.f;

    const float* xg = x + (size_t)(bm * 128) * D_;
    const float* wg = W + (size_t)(bn * 128) * D_;

    for (int kt = 0; kt < D_; kt += 16) {
        #pragma unroll
        for (int w = 0; w < 2; w++) {
            int f4  = tid + w * 256;         // 0..511
            int row = f4 >> 2;               // 0..127
            int kc  = (f4 & 3) << 2;         // 0,4,8,12
            float4 va = *(const float4*)(xg + row * D_ + kt + kc);
            As[kc+0][row] = va.x; As[kc+1][row] = va.y;
            As[kc+2][row] = va.z; As[kc+3][row] = va.w;
            float4 vb = *(const float4*)(wg + row * D_ + kt + kc);
            Bs[kc+0][row] = vb.x; Bs[kc+1][row] = vb.y;
            Bs[kc+2][row] = vb.z; Bs[kc+3][row] = vb.w;
        }
        __syncthreads();
        #pragma unroll
        for (int k = 0; k < 16; k++) {
            float a[8], b[8];
            *(float4*)(a)   = *(const float4*)&As[k][tm*8];
            *(float4*)(a+4) = *(const float4*)&As[k][tm*8+4];
            *(float4*)(b)   = *(const float4*)&Bs[k][tn*8];
            *(float4*)(b+4) = *(const float4*)&Bs[k][tn*8+4];
            #pragma unroll
            for (int i = 0; i < 8; i++)
                #pragma unroll
                for (int j = 0; j < 8; j++)
                    acc[i][j] += a[i] * b[j];
        }
        __syncthreads();
    }

    // Epilogue: scatter. BN==128 => head = bn, b index constant per tile.
    const int b0 = (bm * 128) / S_;
    const int s0 = (bm * 128) % S_;
    const int h  = bn;
    float bvals[8];
    #pragma unroll
    for (int j = 0; j < 8; j++) bvals[j] = bias[bn * 128 + tn * 8 + j];

    #pragma unroll
    for (int i = 0; i < 8; i++) {
        int srow = s0 + tm * 8 + i;
        size_t rowbase = ((size_t)(b0 * H_ + h) * S_ + srow) * DH_;
        #pragma unroll
        for (int j = 0; j < 8; j++) {
            int r = tn * 8 + j;
            int d = r >> 1;
            float v = acc[i][j] + bvals[j];
            if (r & 1) g_k[rowbase + d] = v;
            else       g_q[rowbase + d] = v;
        }
    }
}

// ---------------------------------------------------------------------------
// Kernel 2: center k in-place: k[b,h,s,d] -= mean_s(k[b,h,s,d]).
// One block per (b,h). Fully coalesced (tid%64 = d).
// ---------------------------------------------------------------------------
__global__ __launch_bounds__(256)
void center_k_kernel() {
    __shared__ float red[256];
    __shared__ float mean_s[64];
    const int bh  = blockIdx.x;
    const int tid = threadIdx.x;
    const int d   = tid & 63;
    const int sg  = tid >> 6;    // 0..3
    float* kb = g_k + (size_t)bh * S_ * DH_;

    float sum = 0.f;
    for (int s = sg; s < S_; s += 4) sum += kb[s * DH_ + d];
    red[tid] = sum;
    __syncthreads();
    if (tid < 64)
        mean_s[tid] = (red[tid] + red[tid+64] + red[tid+128] + red[tid+192]) * (1.0f / S_);
    __syncthreads();
    float m = mean_s[d];
    for (int s = sg; s < S_; s += 4) kb[s * DH_ + d] -= m;
}

// ---------------------------------------------------------------------------
// Kernel 3: fused attention.
// attn[i,j] = selu(scale * q_i . k'_j);  out[i,:] = (attn @ v) * S^{-1/2}.
// Block: 128 q-rows (one (b,h)), streams 64-wide j tiles. v read straight from x.
// ---------------------------------------------------------------------------
#define QS_PITCH 132
#define KS_PITCH 68
#define VS_PITCH 68
#define ST_PITCH 132
#define SMEM_FLOATS (64*QS_PITCH + 64*KS_PITCH + 64*VS_PITCH + 64*ST_PITCH)
#define SMEM_BYTES  (SMEM_FLOATS * 4)

__global__ __launch_bounds__(256)
void attn_kernel(const float* __restrict__ x, float* __restrict__ out) {
    extern __shared__ float smf[];
    float* Qs = smf;                    // [d=64][i up to 128] (transposed)
    float* Ks = Qs + 64 * QS_PITCH;     // [d=64][j=64]        (transposed)
    float* Vs = Ks + 64 * KS_PITCH;     // [j=64][d=64]
    float* St = Vs + 64 * VS_PITCH;     // [j=64][i=128]       (selu'd scores, transposed)

    const int tid = threadIdx.x;
    const int it  = blockIdx.x;         // 0..15 (i tile)
    const int bh  = blockIdx.y;         // 0..63
    const int bb  = bh >> 4;
    const int h   = bh & 15;
    const int i0  = it * 128;

    const float* qg = g_q + ((size_t)bh * S_ + i0) * DH_;
    const float* kg = g_k + (size_t)bh * S_ * DH_;

    // Load Q tile [128 x 64] transposed into Qs[d][i]
    #pragma unroll
    for (int w = 0; w < 8; w++) {
        int f4  = tid + w * 256;        // 0..2047
        int row = f4 >> 4;              // 0..127
        int dc  = (f4 & 15) << 2;       // 0..60
        float4 v = *(const float4*)(qg + row * DH_ + dc);
        Qs[(dc+0)*QS_PITCH + row] = v.x;
        Qs[(dc+1)*QS_PITCH + row] = v.y;
        Qs[(dc+2)*QS_PITCH + row] = v.z;
        Qs[(dc+3)*QS_PITCH + row] = v.w;
    }

    float oacc[8][4];
    #pragma unroll
    for (int r = 0; r < 8; r++)
        #pragma unroll
        for (int c = 0; c < 4; c++) oacc[r][c] = 0.f;

    const int tmj = tid >> 5, tni = tid & 31;   // S^T phase: 8 j x 4 i micro
    const int tmi = tid >> 4, tnd = tid & 15;   // O   phase: 8 i x 4 d micro
    const float LAM = 1.0507009873554805f;      // selu lambda
    const float AL  = 1.7580993408473766f;      // lambda * alpha

    for (int jt = 0; jt < S_ / 64; jt++) {
        __syncthreads();   // previous O-phase done reading St/Vs
        const int j0 = jt * 64;
        #pragma unroll
        for (int w = 0; w < 4; w++) {
            int f4  = tid + w * 256;    // 0..1023
            int row = f4 >> 4;          // 0..63
            int dc  = (f4 & 15) << 2;
            float4 kv = *(const float4*)(kg + (size_t)(j0 + row) * DH_ + dc);
            Ks[(dc+0)*KS_PITCH + row] = kv.x;
            Ks[(dc+1)*KS_PITCH + row] = kv.y;
            Ks[(dc+2)*KS_PITCH + row] = kv.z;
            Ks[(dc+3)*KS_PITCH + row] = kv.w;
            float4 vv = *(const float4*)(x + ((size_t)(bb * S_ + j0 + row)) * D_ + h * DH_ + dc);
            *(float4*)&Vs[row * VS_PITCH + dc] = vv;
        }
        __syncthreads();

        // S^T[j][i] = scale * k'_j . q_i
        float sacc[8][4];
        #pragma unroll
        for (int r = 0; r < 8; r++)
            #pragma unroll
            for (int c = 0; c < 4; c++) sacc[r][c] = 0.f;

        #pragma unroll 8
        for (int d = 0; d < 64; d++) {
            float a[8], b[4];
            *(float4*)(a)   = *(const float4*)&Ks[d * KS_PITCH + tmj * 8];
            *(float4*)(a+4) = *(const float4*)&Ks[d * KS_PITCH + tmj * 8 + 4];
            *(float4*)(b)   = *(const float4*)&Qs[d * QS_PITCH + tni * 4];
            #pragma unroll
            for (int r = 0; r < 8; r++)
                #pragma unroll
                for (int c = 0; c < 4; c++)
                    sacc[r][c] += a[r] * b[c];
        }

        // selu + store St[j][i]
        #pragma unroll
        for (int r = 0; r < 8; r++) {
            float4 o;
            float s;
            s = sacc[r][0] * 0.125f; o.x = (s > 0.f) ? LAM * s : AL * (__expf(s) - 1.f);
            s = sacc[r][1] * 0.125f; o.y = (s > 0.f) ? LAM * s : AL * (__expf(s) - 1.f);
            s = sacc[r][2] * 0.125f; o.z = (s > 0.f) ? LAM * s : AL * (__expf(s) - 1.f);
            s = sacc[r][3] * 0.125f; o.w = (s > 0.f) ? LAM * s : AL * (__expf(s) - 1.f);
            *(float4*)&St[(tmj * 8 + r) * ST_PITCH + tni * 4] = o;
        }
        __syncthreads();

        // O[i][d] += sum_j St[j][i] * Vs[j][d]
        #pragma unroll 8
        for (int jj = 0; jj < 64; jj++) {
            float a[8], b[4];
            *(float4*)(a)   = *(const float4*)&St[jj * ST_PITCH + tmi * 8];
            *(float4*)(a+4) = *(const float4*)&St[jj * ST_PITCH + tmi * 8 + 4];
            *(float4*)(b)   = *(const float4*)&Vs[jj * VS_PITCH + tnd * 4];
            #pragma unroll
            for (int r = 0; r < 8; r++)
                #pragma unroll
                for (int c = 0; c < 4; c++)
                    oacc[r][c] += a[r] * b[c];
        }
    }

    // Write out[b, s, h*64 + d] * S^{-1/2}
    const float OS = 0.022097086912079612f;  // 1/sqrt(2048)
    #pragma unroll
    for (int r = 0; r < 8; r++) {
        int srow = i0 + tmi * 8 + r;
        float4 o;
        o.x = oacc[r][0] * OS; o.y = oacc[r][1] * OS;
        o.z = oacc[r][2] * OS; o.w = oacc[r][3] * OS;
        *(float4*)(out + ((size_t)(bb * S_ + srow)) * D_ + h * DH_ + tnd * 4) = o;
    }
}

// ---------------------------------------------------------------------------
extern "C" void kernel_launch(void* const* d_in, const int* in_sizes, int n_in,
                              void* d_out, int out_size) {
    const float* x    = (const float*)d_in[0];
    const float* W    = (const float*)d_in[1];
    const float* bias = (const float*)d_in[2];
    float* out = (float*)d_out;

    cudaFuncSetAttribute(attn_kernel, cudaFuncAttributeMaxDynamicSharedMemorySize, SMEM_BYTES);

    dim3 g1(16, 64);               // N tiles x M tiles
    gemm_qk_kernel<<<g1, 256>>>(x, W, bias);

    center_k_kernel<<<B_ * H_, 256>>>();

    dim3 g3(16, 64);               // i tiles x (b*h)
    attn_kernel<<<g3, 256, SMEM_BYTES>>>(x, out);
}

// round 8
// speedup vs baseline: 2.2271x; 2.2271x over previous
#include <cuda_runtime.h>
#include <math.h>
#include <stdint.h>

#define B_  4
#define S_  2048
#define D_  1024
#define H_  16
#define DH_ 64

// Scratch q/k in [B,H,S,dh] (no runtime alloc -> __device__ globals).
__device__ float g_q[B_*H_*S_*DH_];
__device__ float g_k[B_*H_*S_*DH_];

// ---------------------------------------------------------------------------
// helpers
// ---------------------------------------------------------------------------
__device__ __forceinline__ uint32_t smem_u32(const void* p){
    uint32_t a;
    asm("{ .reg .u64 t; cvta.to.shared.u64 t, %1; cvt.u32.u64 %0, t; }" : "=r"(a) : "l"(p));
    return a;
}
// round-to-nearest tf32 (unbiased; truncation would bias dot products)
__device__ __forceinline__ float f2tf(float x){
    uint32_t r; asm("cvt.rna.tf32.f32 %0, %1;" : "=r"(r) : "f"(x));
    return __uint_as_float(r);
}
__device__ __forceinline__ void ldm4(uint32_t* r, uint32_t addr){
    asm volatile("ldmatrix.sync.aligned.m8n8.x4.shared.b16 {%0,%1,%2,%3}, [%4];"
        : "=r"(r[0]), "=r"(r[1]), "=r"(r[2]), "=r"(r[3]) : "r"(addr));
}
// D(16x8,f32) += A(16x8,tf32) * B(8x8,tf32)
__device__ __forceinline__ void mma8(float* c, const uint32_t* a, uint32_t b0, uint32_t b1){
    asm volatile("mma.sync.aligned.m16n8k8.row.col.f32.tf32.tf32.f32 "
        "{%0,%1,%2,%3}, {%4,%5,%6,%7}, {%8,%9}, {%0,%1,%2,%3};"
        : "+f"(c[0]), "+f"(c[1]), "+f"(c[2]), "+f"(c[3])
        : "r"(a[0]), "r"(a[1]), "r"(a[2]), "r"(a[3]), "r"(b0), "r"(b1));
}

// ---------------------------------------------------------------------------
// Kernel 1: projection. C[m,n] = x[m,:].W[n,:] + b[n]; M=8192 N=2048 K=1024.
// CTA 128x128, 8 warps (warp tile 64x32). K-chunks of 32, reg-staged dbl buf.
// smem pitch 36 f32 (=144B, odd multiple of 16B -> conflict-free ldmatrix).
// Scatter epilogue to g_q (tf32-rounded) / g_k (raw; centered+rounded later).
// ---------------------------------------------------------------------------
#define PJ_PITCH 36
#define PJ_TILE  (128*PJ_PITCH)
#define PJ_SMEM  (4*PJ_TILE*4)      // As[2] + Bs[2]

__global__ __launch_bounds__(256)
void proj_kernel(const float* __restrict__ x, const float* __restrict__ W,
                 const float* __restrict__ bias){
    extern __shared__ float smf[];
    float* As = smf;                 // [2][128][36]
    float* Bs = smf + 2*PJ_TILE;     // [2][128][36]
    const int tid  = threadIdx.x;
    const int lane = tid & 31, wid = tid >> 5;
    const int wm = wid & 1, wn = wid >> 1;     // 2 x 4 warp grid
    const int bn = blockIdx.x, bm = blockIdx.y;
    const int m0 = bm*128, n0 = bn*128;

    // staging: each thread fills 16 elems of A and 16 of B per chunk
    const int srow = tid >> 1;         // 0..127
    const int sk0  = (tid & 1) * 16;   // 0 / 16

    // ldmatrix lane geometry (matrix id m = lane>>3)
    const int am    = lane >> 3;
    const int arow  = (am & 1)*8 + (lane & 7);   // A: m0,m1 rows / m2,m3 rows
    const int acol4 = (am >> 1)*4;               // A: cols +0 / +4
    const int brow  = ((lane>>4)&1)*8 + (lane & 7);  // B: nt / nt+1 rows
    const int bcol4 = ((lane>>3)&1)*4;               // B: cols +0 / +4

    float acc[4][4][4];
    #pragma unroll
    for (int i=0;i<4;i++) 
        #pragma unroll
        for (int j=0;j<4;j++){ acc[i][j][0]=0.f;acc[i][j][1]=0.f;acc[i][j][2]=0.f;acc[i][j][3]=0.f; }

    // preload chunk 0
    #pragma unroll
    for (int i=0;i<4;i++){
        float4 va = *(const float4*)(x + (size_t)(m0+srow)*D_ + sk0 + i*4);
        va.x=f2tf(va.x); va.y=f2tf(va.y); va.z=f2tf(va.z); va.w=f2tf(va.w);
        *(float4*)&As[srow*PJ_PITCH + sk0 + i*4] = va;
        float4 vb = *(const float4*)(W + (size_t)(n0+srow)*D_ + sk0 + i*4);
        vb.x=f2tf(vb.x); vb.y=f2tf(vb.y); vb.z=f2tf(vb.z); vb.w=f2tf(vb.w);
        *(float4*)&Bs[srow*PJ_PITCH + sk0 + i*4] = vb;
    }
    __syncthreads();

    for (int kt = 0; kt < 32; kt++){
        const int cur = kt & 1;
        float4 sa[4], sb[4];
        if (kt+1 < 32){
            const int kb = (kt+1)*32 + sk0;
            #pragma unroll
            for (int i=0;i<4;i++){
                sa[i] = *(const float4*)(x + (size_t)(m0+srow)*D_ + kb + i*4);
                sb[i] = *(const float4*)(W + (size_t)(n0+srow)*D_ + kb + i*4);
            }
        }
        const uint32_t Ab = smem_u32(&As[cur*PJ_TILE]);
        const uint32_t Bb = smem_u32(&Bs[cur*PJ_TILE]);
        #pragma unroll
        for (int kc=0; kc<4; kc++){
            uint32_t a[4][4];
            #pragma unroll
            for (int mt=0; mt<4; mt++)
                ldm4(a[mt], Ab + (uint32_t)(((wm*64 + mt*16 + arow)*PJ_PITCH + kc*8 + acol4)*4));
            #pragma unroll
            for (int ntp=0; ntp<2; ntp++){
                uint32_t b[4];
                ldm4(b, Bb + (uint32_t)(((wn*32 + ntp*16 + brow)*PJ_PITCH + kc*8 + bcol4)*4));
                #pragma unroll
                for (int mt=0; mt<4; mt++){
                    mma8(acc[mt][2*ntp],   a[mt], b[0], b[1]);
                    mma8(acc[mt][2*ntp+1], a[mt], b[2], b[3]);
                }
            }
        }
        if (kt+1 < 32){
            float* An = &As[(cur^1)*PJ_TILE];
            float* Bn = &Bs[(cur^1)*PJ_TILE];
            #pragma unroll
            for (int i=0;i<4;i++){
                float4 va = sa[i];
                va.x=f2tf(va.x); va.y=f2tf(va.y); va.z=f2tf(va.z); va.w=f2tf(va.w);
                *(float4*)&An[srow*PJ_PITCH + sk0 + i*4] = va;
                float4 vb = sb[i];
                vb.x=f2tf(vb.x); vb.y=f2tf(vb.y); vb.z=f2tf(vb.z); vb.w=f2tf(vb.w);
                *(float4*)&Bn[srow*PJ_PITCH + sk0 + i*4] = vb;
            }
        }
        __syncthreads();
    }

    // epilogue: c0=[g][2q](q-part), c1=[g][2q+1](k-part), c2/c3 = rows +8
    const int g = lane >> 2, q2 = lane & 3;
    const int h = bn;                    // N-tile 128 == one head
    #pragma unroll
    for (int mt=0; mt<4; mt++){
        const int row0 = wm*64 + mt*16 + g;
        #pragma unroll
        for (int nt=0; nt<4; nt++){
            const int colq = wn*32 + nt*8 + 2*q2;    // even col -> q
            const float bq = __ldg(&bias[n0 + colq]);
            const float bk = __ldg(&bias[n0 + colq + 1]);
            const int d = colq >> 1;
            #pragma unroll
            for (int half=0; half<2; half++){
                const int m = m0 + row0 + half*8;
                const int b0i = m >> 11, s = m & 2047;
                const size_t base = ((size_t)(b0i*H_ + h)*S_ + s)*DH_ + d;
                g_q[base] = f2tf(acc[mt][nt][half*2+0] + bq);
                g_k[base] =      acc[mt][nt][half*2+1] + bk;
            }
        }
    }
}

// ---------------------------------------------------------------------------
// Kernel 2: center k (exact fp32 mean over S), output tf32-rounded.
// ---------------------------------------------------------------------------
__global__ __launch_bounds__(256)
void center_k_kernel(){
    __shared__ float red[256];
    __shared__ float mean_s[64];
    const int bh = blockIdx.x, tid = threadIdx.x;
    const int d = tid & 63, sg = tid >> 6;
    float* kb = g_k + (size_t)bh * S_ * DH_;
    float sum = 0.f;
    for (int s = sg; s < S_; s += 4) sum += kb[s * DH_ + d];
    red[tid] = sum;
    __syncthreads();
    if (tid < 64)
        mean_s[tid] = (red[tid] + red[tid+64] + red[tid+128] + red[tid+192]) * (1.0f / S_);
    __syncthreads();
    const float mval = mean_s[d];
    for (int s = sg; s < S_; s += 4) kb[s * DH_ + d] = f2tf(kb[s * DH_ + d] - mval);
}

// ---------------------------------------------------------------------------
// Kernel 3: attention. CTA = (b,h, 128 i-rows); 8 warps, warp = m16 strip.
//   mma1: S[16x64] = Q·K'^T (scale folded into Q; exact *0.125)
//   SELU + tf32-round in registers, quad-shuffle repack -> mma2 A-frags
//   mma2: O[16x64] += attn·V^T   (V transposed in smem: Vs[d][j])
// j-tiles of 64, register-staged double buffer. pitch 68 (odd-16B) everywhere.
// ---------------------------------------------------------------------------
#define AP 68
#define AT_SMEM ((128*AP + 4*64*AP)*4)

__global__ __launch_bounds__(256)
void attn_kernel(const float* __restrict__ x, float* __restrict__ out){
    extern __shared__ float smf[];
    float* Qs = smf;                  // [128][68]
    float* Ks = smf + 128*AP;         // [2][64][68]   rows j, cols d
    float* Vs = smf + 128*AP + 2*64*AP; // [2][64][68] rows d, cols j
    const int tid  = threadIdx.x;
    const int lane = tid & 31, wid = tid >> 5;
    const int it = blockIdx.x, bh = blockIdx.y;
    const int bb = bh >> 4, h = bh & 15;
    const int i0 = it * 128;

    const int fr = tid >> 2;            // 0..63 fill row
    const int fd = (tid & 3) * 16;      // fill col base

    // Q fill, fold scale 2^-3 (exact on tf32 values)
    #pragma unroll
    for (int p=0; p<2; p++){
        const float* qg = g_q + ((size_t)bh*S_ + i0 + fr + p*64)*DH_ + fd;
        #pragma unroll
        for (int i=0;i<4;i++){
            float4 v = *(const float4*)(qg + i*4);
            v.x*=0.125f; v.y*=0.125f; v.z*=0.125f; v.w*=0.125f;
            *(float4*)&Qs[(fr + p*64)*AP + fd + i*4] = v;
        }
    }
    // preload K/V tile 0
    {
        const float* kg = g_k + ((size_t)bh*S_ + fr)*DH_ + fd;
        const float* vg = x + ((size_t)(bb*S_ + fr))*D_ + h*DH_ + fd;
        #pragma unroll
        for (int i=0;i<4;i++){
            *(float4*)&Ks[fr*AP + fd + i*4] = *(const float4*)(kg + i*4);
            float4 v = *(const float4*)(vg + i*4);
            Vs[(fd+i*4+0)*AP + fr] = f2tf(v.x);
            Vs[(fd+i*4+1)*AP + fr] = f2tf(v.y);
            Vs[(fd+i*4+2)*AP + fr] = f2tf(v.z);
            Vs[(fd+i*4+3)*AP + fr] = f2tf(v.w);
        }
    }
    __syncthreads();

    // ldmatrix lane geometry
    const int am    = lane >> 3;
    const int arow  = (am & 1)*8 + (lane & 7);
    const int acol4 = (am >> 1)*4;
    const int brow  = ((lane>>4)&1)*8 + (lane & 7);
    const int bcol4 = ((lane>>3)&1)*4;
    // shuffle-repack geometry
    const int  sbase = (lane & ~3) | ((lane & 3) >> 1);
    const bool odd   = lane & 1;

    const float LAM = 1.0507009873554805f;   // selu lambda
    const float AL  = 1.7580993408473766f;   // lambda * alpha

    float oacc[8][4];
    #pragma unroll
    for (int i=0;i<8;i++){ oacc[i][0]=0.f;oacc[i][1]=0.f;oacc[i][2]=0.f;oacc[i][3]=0.f; }

    const uint32_t Qb = smem_u32(Qs);
    const uint32_t aQoff = (uint32_t)(((wid*16 + arow)*AP + acol4)*4);

    for (int jt = 0; jt < 32; jt++){
        const int cur = jt & 1;
        float4 ksg[4], vsg[4];
        if (jt+1 < 32){
            const int j0n = (jt+1)*64;
            const float* kg = g_k + ((size_t)bh*S_ + j0n + fr)*DH_ + fd;
            const float* vg = x + ((size_t)(bb*S_ + j0n + fr))*D_ + h*DH_ + fd;
            #pragma unroll
            for (int i=0;i<4;i++){ ksg[i] = *(const float4*)(kg + i*4);
                                   vsg[i] = *(const float4*)(vg + i*4); }
        }

        // ---- mma1: S = Q . K'^T ----
        float sacc[8][4];
        #pragma unroll
        for (int i=0;i<8;i++){ sacc[i][0]=0.f;sacc[i][1]=0.f;sacc[i][2]=0.f;sacc[i][3]=0.f; }
        const uint32_t Kb = smem_u32(&Ks[cur*64*AP]);
        #pragma unroll
        for (int kc=0; kc<8; kc++){
            uint32_t a[4];
            ldm4(a, Qb + aQoff + (uint32_t)(kc*32));
            #pragma unroll
            for (int ntp=0; ntp<4; ntp++){
                uint32_t b[4];
                ldm4(b, Kb + (uint32_t)(((ntp*16 + brow)*AP + kc*8 + bcol4)*4));
                mma8(sacc[2*ntp],   a, b[0], b[1]);
                mma8(sacc[2*ntp+1], a, b[2], b[3]);
            }
        }

        // ---- SELU + tf32 round (in registers) ----
        #pragma unroll
        for (int nt=0; nt<8; nt++)
            #pragma unroll
            for (int r=0; r<4; r++){
                float v = sacc[nt][r];
                v = (v > 0.f) ? LAM * v : AL * (__expf(v) - 1.f);
                sacc[nt][r] = f2tf(v);
            }

        // ---- mma2: O += attn . V^T ----
        const uint32_t Vb = smem_u32(&Vs[cur*64*AP]);
        #pragma unroll
        for (int jc=0; jc<8; jc++){
            const float s0=sacc[jc][0], s1=sacc[jc][1], s2=sacc[jc][2], s3=sacc[jc][3];
            const float u00=__shfl_sync(0xffffffffu, s0, sbase);
            const float u01=__shfl_sync(0xffffffffu, s1, sbase);
            const float u10=__shfl_sync(0xffffffffu, s0, sbase+2);
            const float u11=__shfl_sync(0xffffffffu, s1, sbase+2);
            const float v00=__shfl_sync(0xffffffffu, s2, sbase);
            const float v01=__shfl_sync(0xffffffffu, s3, sbase);
            const float v10=__shfl_sync(0xffffffffu, s2, sbase+2);
            const float v11=__shfl_sync(0xffffffffu, s3, sbase+2);
            uint32_t a[4];
            a[0] = __float_as_uint(odd ? u01 : u00);   // [g][c]
            a[1] = __float_as_uint(odd ? v01 : v00);   // [g+8][c]
            a[2] = __float_as_uint(odd ? u11 : u10);   // [g][c+4]
            a[3] = __float_as_uint(odd ? v11 : v10);   // [g+8][c+4]
            #pragma unroll
            for (int dtp=0; dtp<4; dtp++){
                uint32_t b[4];
                ldm4(b, Vb + (uint32_t)(((dtp*16 + brow)*AP + jc*8 + bcol4)*4));
                mma8(oacc[2*dtp],   a, b[0], b[1]);
                mma8(oacc[2*dtp+1], a, b[2], b[3]);
            }
        }

        if (jt+1 < 32){
            float* Kn = &Ks[(cur^1)*64*AP];
            float* Vn = &Vs[(cur^1)*64*AP];
            #pragma unroll
            for (int i=0;i<4;i++){
                *(float4*)&Kn[fr*AP + fd + i*4] = ksg[i];
                Vn[(fd+i*4+0)*AP + fr] = f2tf(vsg[i].x);
                Vn[(fd+i*4+1)*AP + fr] = f2tf(vsg[i].y);
                Vn[(fd+i*4+2)*AP + fr] = f2tf(vsg[i].z);
                Vn[(fd+i*4+3)*AP + fr] = f2tf(vsg[i].w);
            }
        }
        __syncthreads();
    }

    // ---- store O * S^-1/2 ----
    const float OS = 0.022097086912079612f;   // 1/sqrt(2048)
    const int g = lane >> 2, q2 = lane & 3;
    #pragma unroll
    for (int dt=0; dt<8; dt++){
        const int d = dt*8 + 2*q2;
        #pragma unroll
        for (int half=0; half<2; half++){
            const int irow = i0 + wid*16 + g + half*8;
            float2 o;
            o.x = oacc[dt][half*2+0] * OS;
            o.y = oacc[dt][half*2+1] * OS;
            *(float2*)(out + ((size_t)(bb*S_ + irow))*D_ + h*DH_ + d) = o;
        }
    }
}

// ---------------------------------------------------------------------------
extern "C" void kernel_launch(void* const* d_in, const int* in_sizes, int n_in,
                              void* d_out, int out_size) {
    const float* x    = (const float*)d_in[0];
    const float* W    = (const float*)d_in[1];
    const float* bias = (const float*)d_in[2];
    float* out = (float*)d_out;

    cudaFuncSetAttribute(proj_kernel, cudaFuncAttributeMaxDynamicSharedMemorySize, PJ_SMEM);
    cudaFuncSetAttribute(attn_kernel, cudaFuncAttributeMaxDynamicSharedMemorySize, AT_SMEM);

    dim3 g1(16, 64);    // N tiles x M tiles
    proj_kernel<<<g1, 256, PJ_SMEM>>>(x, W, bias);

    center_k_kernel<<<B_ * H_, 256>>>();

    dim3 g3(16, 64);    // i tiles x (b*h)
    attn_kernel<<<g3, 256, AT_SMEM>>>(x, out);
}